// round 4
// baseline (speedup 1.0000x reference)
#include <cuda_runtime.h>

// Sobel magnitude: out = sqrt(gx^2 + gy^2 + 1e-4), 3x3 cross-correlation,
// zero padding, x: [64, 1, 512, 512] fp32.
// kx = [[1,0,-1],[2,0,-2],[1,0,-1]]/4 ; ky = [[1,2,1],[0,0,0],[-1,-2,-1]]/4
//
// Separable: a[j]=t+2m+b (-> gx4 = a[k]-a[k+2]); b[j]=t-b (-> gy4 = b[k]+2b[k+1]+b[k+2])
// out = 0.25 * sqrt(gx4^2 + gy4^2 + 16e-4)
//
// blockDim=(32,8). Each thread: 4 px wide (one LDG.128) x 2 output rows
// (3-row sliding register window -> 4 row loads per 2 output rows).
// Horizontal halos via warp shuffle; only edge lanes issue a scalar load.

#define W 512
#define H 512
#define EPS16 1.6e-3f
#define ROWS 2

__device__ __forceinline__ float fast_sqrt(float x) {
    float r;
    asm("sqrt.approx.f32 %0, %1;" : "=f"(r) : "f"(x));
    return r;
}

// Load 6-wide window (cols ox-1 .. ox+4) of row y into c[0..5].
// y is uniform across the warp (blockDim.x == 32).
__device__ __forceinline__ void load_row(const float* __restrict__ base,
                                         int y, int ox, int lane, float* c)
{
    if (y < 0 || y >= H) {
        #pragma unroll
        for (int j = 0; j < 6; ++j) c[j] = 0.0f;
        return;
    }
    const float* row = base + y * W;
    const float4 p = *reinterpret_cast<const float4*>(row + ox);
    c[1] = p.x; c[2] = p.y; c[3] = p.z; c[4] = p.w;
    c[0] = __shfl_up_sync(0xffffffffu, c[4], 1);    // left lane's px3
    c[5] = __shfl_down_sync(0xffffffffu, c[1], 1);  // right lane's px0
    if (lane == 0)  c[0] = (ox > 0)     ? __ldg(row + ox - 1) : 0.0f;
    if (lane == 31) c[5] = (ox + 4 < W) ? __ldg(row + ox + 4) : 0.0f;
}

__global__ __launch_bounds__(256, 5) void sobel_kernel(
    const float* __restrict__ in, float* __restrict__ out)
{
    const int lane = threadIdx.x;                               // 0..31
    const int ox = (blockIdx.x * 32 + lane) * 4;                // 0..508
    const int oy0 = (blockIdx.y * 8 + threadIdx.y) * ROWS;      // 0..510
    const long long img = (long long)blockIdx.z * (W * H);
    const float* base = in + img;
    float* obase = out + img;

    float r[3][6];
    load_row(base, oy0 - 1, ox, lane, r[0]);
    load_row(base, oy0,     ox, lane, r[1]);

    #pragma unroll
    for (int i = 0; i < ROWS; ++i) {
        const int t  = i % 3;
        const int m  = (i + 1) % 3;
        const int bo = (i + 2) % 3;
        load_row(base, oy0 + 1 + i, ox, lane, r[bo]);

        float a[6], b[6];
        #pragma unroll
        for (int j = 0; j < 6; ++j) {
            a[j] = fmaf(2.0f, r[m][j], r[t][j] + r[bo][j]);
            b[j] = r[t][j] - r[bo][j];
        }

        float4 o;
        float* op = reinterpret_cast<float*>(&o);
        #pragma unroll
        for (int k = 0; k < 4; ++k) {
            const float gx4 = a[k] - a[k + 2];
            const float gy4 = fmaf(2.0f, b[k + 1], b[k] + b[k + 2]);
            op[k] = 0.25f * fast_sqrt(fmaf(gx4, gx4, fmaf(gy4, gy4, EPS16)));
        }

        *reinterpret_cast<float4*>(obase + (oy0 + i) * W + ox) = o;
    }
}

extern "C" void kernel_launch(void* const* d_in, const int* in_sizes, int n_in,
                              void* d_out, int out_size)
{
    const float* x = (const float*)d_in[0];
    float* out = (float*)d_out;

    dim3 block(32, 8, 1);                          // 256 threads
    dim3 grid(W / (32 * 4), H / (8 * ROWS), 64);   // 4 x 32 x 64 = 8192 CTAs
    sobel_kernel<<<grid, block>>>(x, out);
}